// round 5
// baseline (speedup 1.0000x reference)
#include <cuda_runtime.h>
#include <cuda_bf16.h>
#include <cstdint>

// ---------------------------------------------------------------------------
// Round 4: identical to Rounds 0-3 (every bench so far died in GPU
// acquisition — broker timeout; the kernel has never executed on hardware).
// Under bench scarcity the information-maximizing submission is still the
// audited baseline: a pass yields a verified reference + ncu profile that
// selects the next (expensive) optimization branch.
//
// Problem constants
//   B=16384, IN=288 (motions 256 + z 32), H1=H2=512, MOE=8, MOTION=128
// ---------------------------------------------------------------------------
#define BQ   16384
#define NEXP 8

// ---------------------------------------------------------------------------
// Device scratch (static — no runtime allocation allowed)
// ---------------------------------------------------------------------------
__device__ __nv_bfloat16 g_X  [(size_t)BQ * 288];
__device__ __nv_bfloat16 g_Zb [(size_t)BQ * 32];
__device__ __nv_bfloat16 g_gw1[288 * 512];
__device__ __nv_bfloat16 g_gw2[512 * 512];
__device__ __nv_bfloat16 g_gw3[512 * 8];
__device__ __nv_bfloat16 g_W1 [(size_t)NEXP * 288 * 512];
__device__ __nv_bfloat16 g_W2 [(size_t)NEXP * 544 * 512];
__device__ __nv_bfloat16 g_W3 [(size_t)NEXP * 544 * 128];
__device__ __nv_bfloat16 g_G1 [(size_t)BQ * 512];
__device__ __nv_bfloat16 g_G2 [(size_t)BQ * 512];
__device__ __nv_bfloat16 g_H1 [(size_t)NEXP * BQ * 512];
__device__ __nv_bfloat16 g_H2 [(size_t)NEXP * BQ * 512];
__device__ __nv_bfloat16 g_H3 [(size_t)NEXP * BQ * 128];
__device__ float         g_para[(size_t)BQ * 8];
__device__ float         g_part[256];
__device__ float         g_invnorm;

__device__ __forceinline__ float eluf(float x) {
    return x > 0.f ? x : (__expf(x) - 1.f);
}

// ---------------------------------------------------------------------------
// fp32 -> bf16 conversion
// ---------------------------------------------------------------------------
__global__ void cvt_kernel(const float* __restrict__ s, __nv_bfloat16* __restrict__ d, int n) {
    int i = blockIdx.x * 256 + threadIdx.x;
    if (i < n) d[i] = __float2bfloat16(s[i]);
}

// Build X = concat(motions[B,256], z[B,32]) in bf16, plus Z in bf16
__global__ void buildx_kernel(const float* __restrict__ motions, const float* __restrict__ z,
                              __nv_bfloat16* __restrict__ X, __nv_bfloat16* __restrict__ Z) {
    int i = blockIdx.x * 256 + threadIdx.x;          // 0 .. B*288-1
    int b = i / 288, c = i % 288;
    float v = (c < 256) ? motions[(size_t)b * 256 + c] : z[(size_t)b * 32 + (c - 256)];
    X[i] = __float2bfloat16(v);
    if (i < BQ * 32) Z[i] = __float2bfloat16(z[i]);
}

// ---------------------------------------------------------------------------
// GEMM: C[M,N] = ELU( concat(A1[M,K1], A2[M,K2]) @ W[K1+K2, N] + bias[N] )
// bf16 inputs, fp32 accumulation (mma.sync.m16n8k16), bf16 output.
// BM=128, BN=128, BK=32, 256 threads (8 warps, 4x2), warp tile 32x64.
// blockIdx.z selects expert via the stride parameters.
// ---------------------------------------------------------------------------
__global__ __launch_bounds__(256)
void gemm_elu(const __nv_bfloat16* __restrict__ A1,
              const __nv_bfloat16* __restrict__ A2,
              const __nv_bfloat16* __restrict__ W,
              const float* __restrict__ bias,
              __nv_bfloat16* __restrict__ C,
              int N, int K1, int K2,
              long long sA1, long long sW, long long sB, long long sC)
{
    const int e = blockIdx.z;
    A1   += (size_t)e * sA1;
    W    += (size_t)e * sW;
    bias += (size_t)e * sB;
    C    += (size_t)e * sC;

    const int m0 = blockIdx.y * 128;
    const int n0 = blockIdx.x * 128;

    __shared__ __nv_bfloat16 As[2][128][40];   // A tile, row-major, +8 pad
    __shared__ __nv_bfloat16 Ws[2][128][34];   // W tile TRANSPOSED: [n][k], +2 pad

    const int tid  = threadIdx.x;
    const int warp = tid >> 5, lane = tid & 31;
    const int wm   = (warp >> 1) * 32, wn = (warp & 1) * 64;
    const int grp  = lane >> 2, qid = lane & 3;

    const int arow = tid >> 2,  acol = (tid & 3) * 8;   // A tile loader coords
    const int wk   = tid >> 4,  wnc  = (tid & 15) * 8;  // W tile loader coords

    const int nk = (K1 + K2) >> 5;

    float acc[2][8][4];
    #pragma unroll
    for (int i = 0; i < 2; i++)
        #pragma unroll
        for (int j = 0; j < 8; j++)
            #pragma unroll
            for (int q = 0; q < 4; q++) acc[i][j][q] = 0.f;

    auto fetchA = [&](int kt, uint4& v0, uint4& v1) {
        int k0 = kt << 5;
        const __nv_bfloat16* src; int ks, kl;
        if (k0 < K1) { src = A1; ks = K1; kl = k0; }
        else         { src = A2; ks = K2; kl = k0 - K1; }
        v0 = *reinterpret_cast<const uint4*>(src + (size_t)(m0 + arow)      * ks + kl + acol);
        v1 = *reinterpret_cast<const uint4*>(src + (size_t)(m0 + arow + 64) * ks + kl + acol);
    };
    auto fetchW = [&](int kt, uint4& v0, uint4& v1) {
        int k0 = kt << 5;
        v0 = *reinterpret_cast<const uint4*>(W + (size_t)(k0 + wk)      * N + n0 + wnc);
        v1 = *reinterpret_cast<const uint4*>(W + (size_t)(k0 + wk + 16) * N + n0 + wnc);
    };
    auto stsAll = [&](int buf, uint4 a0, uint4 a1, uint4 w0, uint4 w1) {
        *reinterpret_cast<uint4*>(&As[buf][arow][acol])      = a0;
        *reinterpret_cast<uint4*>(&As[buf][arow + 64][acol]) = a1;
        union U { uint4 u; __nv_bfloat16 h[8]; } c0, c1;
        c0.u = w0; c1.u = w1;
        #pragma unroll
        for (int j = 0; j < 8; j++) {
            Ws[buf][wnc + j][wk]      = c0.h[j];
            Ws[buf][wnc + j][wk + 16] = c1.h[j];
        }
    };

    uint4 ra0, ra1, rw0, rw1;
    fetchA(0, ra0, ra1); fetchW(0, rw0, rw1);
    stsAll(0, ra0, ra1, rw0, rw1);
    __syncthreads();

    for (int kt = 0; kt < nk; ++kt) {
        const int buf = kt & 1;
        if (kt + 1 < nk) { fetchA(kt + 1, ra0, ra1); fetchW(kt + 1, rw0, rw1); }

        #pragma unroll
        for (int kk = 0; kk < 2; kk++) {
            uint32_t af[2][4], bfv[8][2];
            const int c = kk * 16 + qid * 2;
            #pragma unroll
            for (int mi = 0; mi < 2; mi++) {
                int r = wm + mi * 16 + grp;
                af[mi][0] = *reinterpret_cast<const uint32_t*>(&As[buf][r][c]);
                af[mi][1] = *reinterpret_cast<const uint32_t*>(&As[buf][r + 8][c]);
                af[mi][2] = *reinterpret_cast<const uint32_t*>(&As[buf][r][c + 8]);
                af[mi][3] = *reinterpret_cast<const uint32_t*>(&As[buf][r + 8][c + 8]);
            }
            #pragma unroll
            for (int ni = 0; ni < 8; ni++) {
                int n = wn + ni * 8 + grp;
                bfv[ni][0] = *reinterpret_cast<const uint32_t*>(&Ws[buf][n][c]);
                bfv[ni][1] = *reinterpret_cast<const uint32_t*>(&Ws[buf][n][c + 8]);
            }
            #pragma unroll
            for (int mi = 0; mi < 2; mi++)
                #pragma unroll
                for (int ni = 0; ni < 8; ni++) {
                    float* cc = acc[mi][ni];
                    asm volatile(
                        "mma.sync.aligned.m16n8k16.row.col.f32.bf16.bf16.f32 "
                        "{%0,%1,%2,%3}, {%4,%5,%6,%7}, {%8,%9}, {%0,%1,%2,%3};\n"
                        : "+f"(cc[0]), "+f"(cc[1]), "+f"(cc[2]), "+f"(cc[3])
                        : "r"(af[mi][0]), "r"(af[mi][1]), "r"(af[mi][2]), "r"(af[mi][3]),
                          "r"(bfv[ni][0]), "r"(bfv[ni][1]));
                }
        }

        if (kt + 1 < nk) stsAll(buf ^ 1, ra0, ra1, rw0, rw1);
        __syncthreads();
    }

    // Epilogue: bias + ELU, bf16 stores
    #pragma unroll
    for (int mi = 0; mi < 2; mi++) {
        #pragma unroll
        for (int ni = 0; ni < 8; ni++) {
            int row = m0 + wm + mi * 16 + grp;
            int col = n0 + wn + ni * 8 + qid * 2;
            float b0 = bias[col], b1 = bias[col + 1];
            float v0 = eluf(acc[mi][ni][0] + b0);
            float v1 = eluf(acc[mi][ni][1] + b1);
            float v2 = eluf(acc[mi][ni][2] + b0);
            float v3 = eluf(acc[mi][ni][3] + b1);
            __nv_bfloat162 p0, p1;
            p0.x = __float2bfloat16(v0); p0.y = __float2bfloat16(v1);
            p1.x = __float2bfloat16(v2); p1.y = __float2bfloat16(v3);
            *reinterpret_cast<__nv_bfloat162*>(C + (size_t)row * N + col)       = p0;
            *reinterpret_cast<__nv_bfloat162*>(C + (size_t)(row + 8) * N + col) = p1;
        }
    }
}

// ---------------------------------------------------------------------------
// Gate layer 3: para[B,8] = ELU(G2[B,512] @ gw3[512,8] + gb3)
// One warp per row.
// ---------------------------------------------------------------------------
__global__ __launch_bounds__(256)
void gate3_kernel(const __nv_bfloat16* __restrict__ G2,
                  const __nv_bfloat16* __restrict__ gw3,
                  const float* __restrict__ gb3,
                  float* __restrict__ para)
{
    __shared__ __nv_bfloat16 sw[512 * 8];
    for (int i = threadIdx.x; i < 512 * 8; i += 256) sw[i] = gw3[i];
    __syncthreads();

    const int warp = threadIdx.x >> 5, lane = threadIdx.x & 31;
    const int r = blockIdx.x * 8 + warp;
    const __nv_bfloat16* g = G2 + (size_t)r * 512;

    float acc[8];
    #pragma unroll
    for (int j = 0; j < 8; j++) acc[j] = 0.f;

    for (int i = 0; i < 16; i++) {
        int k = i * 32 + lane;
        float gv = __bfloat162float(g[k]);
        #pragma unroll
        for (int j = 0; j < 8; j++)
            acc[j] += gv * __bfloat162float(sw[k * 8 + j]);
    }
    #pragma unroll
    for (int j = 0; j < 8; j++)
        #pragma unroll
        for (int off = 16; off; off >>= 1)
            acc[j] += __shfl_xor_sync(0xFFFFFFFFu, acc[j], off);

    if (lane == 0) {
        #pragma unroll
        for (int j = 0; j < 8; j++)
            para[(size_t)r * 8 + j] = eluf(acc[j] + gb3[j]);
    }
}

// ---------------------------------------------------------------------------
// Frobenius norm of para: two-stage deterministic reduction
// ---------------------------------------------------------------------------
__global__ void sumsq_kernel(const float* __restrict__ para) {
    __shared__ float sh[256];
    float s = 0.f;
    for (int i = blockIdx.x * 256 + threadIdx.x; i < BQ * 8; i += 256 * 256)
        s += para[i] * para[i];
    sh[threadIdx.x] = s; __syncthreads();
    for (int o = 128; o; o >>= 1) {
        if (threadIdx.x < o) sh[threadIdx.x] += sh[threadIdx.x + o];
        __syncthreads();
    }
    if (threadIdx.x == 0) g_part[blockIdx.x] = sh[0];
}

__global__ void norminv_kernel() {
    __shared__ float sh[256];
    sh[threadIdx.x] = g_part[threadIdx.x]; __syncthreads();
    for (int o = 128; o; o >>= 1) {
        if (threadIdx.x < o) sh[threadIdx.x] += sh[threadIdx.x + o];
        __syncthreads();
    }
    if (threadIdx.x == 0) g_invnorm = 1.f / sqrtf(sh[0]);
}

// ---------------------------------------------------------------------------
// Final combine: out[b,m] = sigmoid( invnorm * sum_e para[b,e]*H3[e,b,m] )
// ---------------------------------------------------------------------------
__global__ __launch_bounds__(256)
void final_kernel(const __nv_bfloat16* __restrict__ H3,
                  const float* __restrict__ para,
                  float* __restrict__ out)
{
    int idx = blockIdx.x * 256 + threadIdx.x;   // 0 .. B*128-1
    int b = idx >> 7;
    float inv = g_invnorm;
    float s = 0.f;
    #pragma unroll
    for (int e = 0; e < NEXP; e++)
        s += para[(size_t)b * 8 + e] *
             __bfloat162float(H3[(size_t)e * BQ * 128 + idx]);
    float t = s * inv;
    out[idx] = 1.f / (1.f + __expf(-t));
}

// ---------------------------------------------------------------------------
// Host launcher (graph-capturable: kernel launches only)
// ---------------------------------------------------------------------------
extern "C" void kernel_launch(void* const* d_in, const int* in_sizes, int n_in,
                              void* d_out, int out_size)
{
    const float* motions = (const float*)d_in[0];
    const float* z       = (const float*)d_in[1];
    const float* gw1     = (const float*)d_in[2];
    const float* gb1     = (const float*)d_in[3];
    const float* gw2     = (const float*)d_in[4];
    const float* gb2     = (const float*)d_in[5];
    const float* gw3     = (const float*)d_in[6];
    const float* gb3     = (const float*)d_in[7];
    const float* W1      = (const float*)d_in[8];
    const float* b1      = (const float*)d_in[9];
    const float* W2      = (const float*)d_in[10];
    const float* b2      = (const float*)d_in[11];
    const float* W3      = (const float*)d_in[12];
    const float* b3      = (const float*)d_in[13];
    float* out = (float*)d_out;

    void *pX, *pZ, *pgw1, *pgw2, *pgw3, *pW1, *pW2, *pW3;
    void *pG1, *pG2, *pH1, *pH2, *pH3, *ppara;
    cudaGetSymbolAddress(&pX,   g_X);
    cudaGetSymbolAddress(&pZ,   g_Zb);
    cudaGetSymbolAddress(&pgw1, g_gw1);
    cudaGetSymbolAddress(&pgw2, g_gw2);
    cudaGetSymbolAddress(&pgw3, g_gw3);
    cudaGetSymbolAddress(&pW1,  g_W1);
    cudaGetSymbolAddress(&pW2,  g_W2);
    cudaGetSymbolAddress(&pW3,  g_W3);
    cudaGetSymbolAddress(&pG1,  g_G1);
    cudaGetSymbolAddress(&pG2,  g_G2);
    cudaGetSymbolAddress(&pH1,  g_H1);
    cudaGetSymbolAddress(&pH2,  g_H2);
    cudaGetSymbolAddress(&pH3,  g_H3);
    cudaGetSymbolAddress(&ppara, g_para);

    typedef __nv_bfloat16 bf;

    // Convert weights to bf16 + build X/Z
    cvt_kernel<<<576,  256>>>(gw1, (bf*)pgw1, 288 * 512);
    cvt_kernel<<<1024, 256>>>(gw2, (bf*)pgw2, 512 * 512);
    cvt_kernel<<<16,   256>>>(gw3, (bf*)pgw3, 512 * 8);
    cvt_kernel<<<4608, 256>>>(W1,  (bf*)pW1,  NEXP * 288 * 512);
    cvt_kernel<<<8704, 256>>>(W2,  (bf*)pW2,  NEXP * 544 * 512);
    cvt_kernel<<<2176, 256>>>(W3,  (bf*)pW3,  NEXP * 544 * 128);
    buildx_kernel<<<BQ * 288 / 256, 256>>>(motions, z, (bf*)pX, (bf*)pZ);

    // Gate MLP
    gemm_elu<<<dim3(4, 128, 1), 256>>>((bf*)pX, nullptr, (bf*)pgw1, gb1, (bf*)pG1,
                                       512, 288, 0, 0, 0, 0, 0);
    gemm_elu<<<dim3(4, 128, 1), 256>>>((bf*)pG1, nullptr, (bf*)pgw2, gb2, (bf*)pG2,
                                       512, 512, 0, 0, 0, 0, 0);
    gate3_kernel<<<BQ / 8, 256>>>((bf*)pG2, (bf*)pgw3, gb3, (float*)ppara);
    sumsq_kernel<<<256, 256>>>((float*)ppara);
    norminv_kernel<<<1, 256>>>();

    // Experts (blockIdx.z = expert)
    gemm_elu<<<dim3(4, 128, NEXP), 256>>>((bf*)pX, nullptr, (bf*)pW1, b1, (bf*)pH1,
                                          512, 288, 0,
                                          0, (long long)288 * 512, 512, (long long)BQ * 512);
    gemm_elu<<<dim3(4, 128, NEXP), 256>>>((bf*)pH1, (bf*)pZ, (bf*)pW2, b2, (bf*)pH2,
                                          512, 512, 32,
                                          (long long)BQ * 512, (long long)544 * 512, 512,
                                          (long long)BQ * 512);
    gemm_elu<<<dim3(1, 128, NEXP), 256>>>((bf*)pH2, (bf*)pZ, (bf*)pW3, b3, (bf*)pH3,
                                          128, 512, 32,
                                          (long long)BQ * 512, (long long)544 * 128, 128,
                                          (long long)BQ * 128);

    // Gated combine + norm + sigmoid
    final_kernel<<<BQ * 128 / 256, 256>>>((bf*)pH3, (float*)ppara, out);
}

// round 8
// speedup vs baseline: 1.5323x; 1.5323x over previous
#include <cuda_runtime.h>
#include <cuda_bf16.h>
#include <cstdint>

// ---------------------------------------------------------------------------
// Round 7: identical to Rounds 5/6 (broker timeouts; the cp.async + ldmatrix
// GEMM has never run). Audited twice; resubmitting so the next successful
// bench tests the highest-EV candidate with clean single-delta attribution
// against the validated 983us baseline.
//
// vs. baseline:
//   - cp.async (LDGSTS) 3-stage pipeline, 16B transfers, 48KB smem
//   - both tiles row-major with XOR swizzle (no transpose STS)
//   - ldmatrix.x4 (A) / ldmatrix.x4.trans (B) fragment loads
//
// B=16384, IN=288 (motions 256 + z 32), H1=H2=512, MOE=8, MOTION=128
// ---------------------------------------------------------------------------
#define BQ   16384
#define NEXP 8

__device__ __nv_bfloat16 g_X  [(size_t)BQ * 288];
__device__ __nv_bfloat16 g_Zb [(size_t)BQ * 32];
__device__ __nv_bfloat16 g_gw1[288 * 512];
__device__ __nv_bfloat16 g_gw2[512 * 512];
__device__ __nv_bfloat16 g_gw3[512 * 8];
__device__ __nv_bfloat16 g_W1 [(size_t)NEXP * 288 * 512];
__device__ __nv_bfloat16 g_W2 [(size_t)NEXP * 544 * 512];
__device__ __nv_bfloat16 g_W3 [(size_t)NEXP * 544 * 128];
__device__ __nv_bfloat16 g_G1 [(size_t)BQ * 512];
__device__ __nv_bfloat16 g_G2 [(size_t)BQ * 512];
__device__ __nv_bfloat16 g_H1 [(size_t)NEXP * BQ * 512];
__device__ __nv_bfloat16 g_H2 [(size_t)NEXP * BQ * 512];
__device__ __nv_bfloat16 g_H3 [(size_t)NEXP * BQ * 128];
__device__ float         g_para[(size_t)BQ * 8];
__device__ float         g_part[256];
__device__ float         g_invnorm;

__device__ __forceinline__ float eluf(float x) {
    return x > 0.f ? x : (__expf(x) - 1.f);
}

// ---------------------------------------------------------------------------
// fp32 -> bf16 conversion (vectorized: float4 -> 2x bf16x2)
// ---------------------------------------------------------------------------
__global__ void cvt4_kernel(const float4* __restrict__ s, uint2* __restrict__ d, int n4) {
    int i = blockIdx.x * 256 + threadIdx.x;
    if (i < n4) {
        float4 v = s[i];
        __nv_bfloat162 lo = __floats2bfloat162_rn(v.x, v.y);
        __nv_bfloat162 hi = __floats2bfloat162_rn(v.z, v.w);
        uint2 o;
        o.x = *reinterpret_cast<uint32_t*>(&lo);
        o.y = *reinterpret_cast<uint32_t*>(&hi);
        d[i] = o;
    }
}

// Build X = concat(motions[B,256], z[B,32]) in bf16, plus Z in bf16
__global__ void buildx_kernel(const float* __restrict__ motions, const float* __restrict__ z,
                              __nv_bfloat16* __restrict__ X, __nv_bfloat16* __restrict__ Z) {
    int i = blockIdx.x * 256 + threadIdx.x;          // 0 .. B*288-1
    int b = i / 288, c = i % 288;
    float v = (c < 256) ? motions[(size_t)b * 256 + c] : z[(size_t)b * 32 + (c - 256)];
    X[i] = __float2bfloat16(v);
    if (i < BQ * 32) Z[i] = __float2bfloat16(z[i]);
}

// ---------------------------------------------------------------------------
// GEMM: C[M,N] = ELU( concat(A1[M,K1], A2[M,K2]) @ W[K1+K2, N] + bias[N] )
// bf16 in, fp32 accum (mma.sync.m16n8k16), bf16 out.
// BM=128, BN=128, BK=32, 256 threads (8 warps 4x2), warp tile 32x64.
// cp.async 3-stage pipeline; swizzled row-major smem; ldmatrix fragments.
// ---------------------------------------------------------------------------
#define STAGES 3

__device__ __forceinline__ void ldsm_x4(uint32_t addr, uint32_t& r0, uint32_t& r1,
                                        uint32_t& r2, uint32_t& r3) {
    asm volatile("ldmatrix.sync.aligned.m8n8.x4.shared.b16 {%0,%1,%2,%3}, [%4];"
                 : "=r"(r0), "=r"(r1), "=r"(r2), "=r"(r3) : "r"(addr));
}
__device__ __forceinline__ void ldsm_x4_t(uint32_t addr, uint32_t& r0, uint32_t& r1,
                                          uint32_t& r2, uint32_t& r3) {
    asm volatile("ldmatrix.sync.aligned.m8n8.x4.trans.shared.b16 {%0,%1,%2,%3}, [%4];"
                 : "=r"(r0), "=r"(r1), "=r"(r2), "=r"(r3) : "r"(addr));
}

__global__ __launch_bounds__(256)
void gemm_elu(const __nv_bfloat16* __restrict__ A1,
              const __nv_bfloat16* __restrict__ A2,
              const __nv_bfloat16* __restrict__ W,
              const float* __restrict__ bias,
              __nv_bfloat16* __restrict__ C,
              int N, int K1, int K2,
              long long sA1, long long sW, long long sB, long long sC)
{
    const int e = blockIdx.z;
    A1   += (size_t)e * sA1;
    W    += (size_t)e * sW;
    bias += (size_t)e * sB;
    C    += (size_t)e * sC;

    const int m0 = blockIdx.y * 128;
    const int n0 = blockIdx.x * 128;

    // A stage: 128 rows x 64B (4 chunks of 16B), swizzle chunk ^ ((row>>1)&3)
    // W stage: 32 rows  x 256B (16 chunks),      swizzle chunk ^ (k&7)
    __shared__ __align__(16) unsigned char smem[STAGES * 8192 * 2];   // 48 KB
    const uint32_t smemA = (uint32_t)__cvta_generic_to_shared(smem);
    const uint32_t smemW = smemA + STAGES * 8192;

    const int tid  = threadIdx.x;
    const int warp = tid >> 5, lane = tid & 31;
    const int wm   = (warp >> 1) * 32, wn = (warp & 1) * 64;
    const int grp  = lane >> 2, qid = lane & 3;

    const int nk = (K1 + K2) >> 5;

    float acc[2][8][4];
    #pragma unroll
    for (int i = 0; i < 2; i++)
        #pragma unroll
        for (int j = 0; j < 8; j++)
            #pragma unroll
            for (int q = 0; q < 4; q++) acc[i][j][q] = 0.f;

    // cp.async issue for K-tile kt into stage s
    auto issue = [&](int s, int kt) {
        const int k0 = kt << 5;
        // ---- A tile: thread (row = tid>>1, chunks (tid&1)*2 + {0,1})
        const __nv_bfloat16* src; int ks, kl;
        if (k0 < K1) { src = A1; ks = K1; kl = k0; }
        else         { src = A2; ks = K2; kl = k0 - K1; }
        const int ar = tid >> 1;
        const uint32_t ab = smemA + s * 8192;
        #pragma unroll
        for (int i = 0; i < 2; i++) {
            int ch = (tid & 1) * 2 + i;
            uint32_t dst = ab + (uint32_t)((ar * 4 + (ch ^ ((ar >> 1) & 3))) * 16);
            const void* g = src + (size_t)(m0 + ar) * ks + kl + ch * 8;
            asm volatile("cp.async.cg.shared.global [%0], [%1], 16;" :: "r"(dst), "l"(g));
        }
        // ---- W tile: thread (k = tid>>3, chunks (tid&7)*2 + {0,1})
        const int wr = tid >> 3;
        const uint32_t wb = smemW + s * 8192;
        #pragma unroll
        for (int i = 0; i < 2; i++) {
            int ch = (tid & 7) * 2 + i;
            uint32_t dst = wb + (uint32_t)((wr * 16 + (ch ^ (wr & 7))) * 16);
            const void* g = W + (size_t)(k0 + wr) * N + n0 + ch * 8;
            asm volatile("cp.async.cg.shared.global [%0], [%1], 16;" :: "r"(dst), "l"(g));
        }
    };

    // prologue: fill STAGES-1 stages
    #pragma unroll
    for (int s = 0; s < STAGES - 1; s++) {
        issue(s, s);
        asm volatile("cp.async.commit_group;");
    }

    for (int kt = 0; kt < nk; ++kt) {
        asm volatile("cp.async.wait_group 1;");   // stage kt resident
        __syncthreads();

        const int pf = kt + STAGES - 1;
        if (pf < nk) issue(pf % STAGES, pf);
        asm volatile("cp.async.commit_group;");

        const int buf = kt % STAGES;
        const uint32_t ab = smemA + buf * 8192;
        const uint32_t wb = smemW + buf * 8192;

        #pragma unroll
        for (int kk = 0; kk < 2; kk++) {
            // A fragments: ldmatrix.x4 per (mi)
            uint32_t af[2][4];
            #pragma unroll
            for (int mi = 0; mi < 2; mi++) {
                int row = wm + mi * 16 + (lane & 15);
                int ch  = kk * 2 + (lane >> 4);
                uint32_t addr = ab + (uint32_t)((row * 4 + (ch ^ ((row >> 1) & 3))) * 16);
                ldsm_x4(addr, af[mi][0], af[mi][1], af[mi][2], af[mi][3]);
            }
            // B fragments: ldmatrix.x4.trans per (n2) -> covers 2 n-blocks
            uint32_t bfr[4][4];
            #pragma unroll
            for (int n2 = 0; n2 < 4; n2++) {
                int k  = kk * 16 + (lane & 15);
                int ch = (wn >> 3) + n2 * 2 + (lane >> 4);
                uint32_t addr = wb + (uint32_t)((k * 16 + (ch ^ (k & 7))) * 16);
                ldsm_x4_t(addr, bfr[n2][0], bfr[n2][1], bfr[n2][2], bfr[n2][3]);
            }
            #pragma unroll
            for (int mi = 0; mi < 2; mi++)
                #pragma unroll
                for (int ni = 0; ni < 8; ni++) {
                    float* cc = acc[mi][ni];
                    uint32_t b0 = bfr[ni >> 1][(ni & 1) * 2];
                    uint32_t b1 = bfr[ni >> 1][(ni & 1) * 2 + 1];
                    asm volatile(
                        "mma.sync.aligned.m16n8k16.row.col.f32.bf16.bf16.f32 "
                        "{%0,%1,%2,%3}, {%4,%5,%6,%7}, {%8,%9}, {%0,%1,%2,%3};\n"
                        : "+f"(cc[0]), "+f"(cc[1]), "+f"(cc[2]), "+f"(cc[3])
                        : "r"(af[mi][0]), "r"(af[mi][1]), "r"(af[mi][2]), "r"(af[mi][3]),
                          "r"(b0), "r"(b1));
                }
        }
    }

    // Epilogue: bias + ELU, bf16 stores (identical to validated baseline)
    #pragma unroll
    for (int mi = 0; mi < 2; mi++) {
        #pragma unroll
        for (int ni = 0; ni < 8; ni++) {
            int row = m0 + wm + mi * 16 + grp;
            int col = n0 + wn + ni * 8 + qid * 2;
            float b0 = bias[col], b1 = bias[col + 1];
            float v0 = eluf(acc[mi][ni][0] + b0);
            float v1 = eluf(acc[mi][ni][1] + b1);
            float v2 = eluf(acc[mi][ni][2] + b0);
            float v3 = eluf(acc[mi][ni][3] + b1);
            __nv_bfloat162 p0, p1;
            p0.x = __float2bfloat16(v0); p0.y = __float2bfloat16(v1);
            p1.x = __float2bfloat16(v2); p1.y = __float2bfloat16(v3);
            *reinterpret_cast<__nv_bfloat162*>(C + (size_t)row * N + col)       = p0;
            *reinterpret_cast<__nv_bfloat162*>(C + (size_t)(row + 8) * N + col) = p1;
        }
    }
}

// ---------------------------------------------------------------------------
// Gate layer 3: para[B,8] = ELU(G2[B,512] @ gw3[512,8] + gb3). One warp/row.
// ---------------------------------------------------------------------------
__global__ __launch_bounds__(256)
void gate3_kernel(const __nv_bfloat16* __restrict__ G2,
                  const __nv_bfloat16* __restrict__ gw3,
                  const float* __restrict__ gb3,
                  float* __restrict__ para)
{
    __shared__ __nv_bfloat16 sw[512 * 8];
    for (int i = threadIdx.x; i < 512 * 8; i += 256) sw[i] = gw3[i];
    __syncthreads();

    const int warp = threadIdx.x >> 5, lane = threadIdx.x & 31;
    const int r = blockIdx.x * 8 + warp;
    const __nv_bfloat16* g = G2 + (size_t)r * 512;

    float acc[8];
    #pragma unroll
    for (int j = 0; j < 8; j++) acc[j] = 0.f;

    for (int i = 0; i < 16; i++) {
        int k = i * 32 + lane;
        float gv = __bfloat162float(g[k]);
        #pragma unroll
        for (int j = 0; j < 8; j++)
            acc[j] += gv * __bfloat162float(sw[k * 8 + j]);
    }
    #pragma unroll
    for (int j = 0; j < 8; j++)
        #pragma unroll
        for (int off = 16; off; off >>= 1)
            acc[j] += __shfl_xor_sync(0xFFFFFFFFu, acc[j], off);

    if (lane == 0) {
        #pragma unroll
        for (int j = 0; j < 8; j++)
            para[(size_t)r * 8 + j] = eluf(acc[j] + gb3[j]);
    }
}

// ---------------------------------------------------------------------------
// Frobenius norm of para: two-stage deterministic reduction
// ---------------------------------------------------------------------------
__global__ void sumsq_kernel(const float* __restrict__ para) {
    __shared__ float sh[256];
    float s = 0.f;
    for (int i = blockIdx.x * 256 + threadIdx.x; i < BQ * 8; i += 256 * 256)
        s += para[i] * para[i];
    sh[threadIdx.x] = s; __syncthreads();
    for (int o = 128; o; o >>= 1) {
        if (threadIdx.x < o) sh[threadIdx.x] += sh[threadIdx.x + o];
        __syncthreads();
    }
    if (threadIdx.x == 0) g_part[blockIdx.x] = sh[0];
}

__global__ void norminv_kernel() {
    __shared__ float sh[256];
    sh[threadIdx.x] = g_part[threadIdx.x]; __syncthreads();
    for (int o = 128; o; o >>= 1) {
        if (threadIdx.x < o) sh[threadIdx.x] += sh[threadIdx.x + o];
        __syncthreads();
    }
    if (threadIdx.x == 0) g_invnorm = 1.f / sqrtf(sh[0]);
}

// ---------------------------------------------------------------------------
// Final combine: out[b,m] = sigmoid( invnorm * sum_e para[b,e]*H3[e,b,m] )
// ---------------------------------------------------------------------------
__global__ __launch_bounds__(256)
void final_kernel(const __nv_bfloat16* __restrict__ H3,
                  const float* __restrict__ para,
                  float* __restrict__ out)
{
    int idx = blockIdx.x * 256 + threadIdx.x;   // 0 .. B*128-1
    int b = idx >> 7;
    float inv = g_invnorm;
    float s = 0.f;
    #pragma unroll
    for (int e = 0; e < NEXP; e++)
        s += para[(size_t)b * 8 + e] *
             __bfloat162float(H3[(size_t)e * BQ * 128 + idx]);
    float t = s * inv;
    out[idx] = 1.f / (1.f + __expf(-t));
}

// ---------------------------------------------------------------------------
// Host launcher (graph-capturable: kernel launches only)
// ---------------------------------------------------------------------------
extern "C" void kernel_launch(void* const* d_in, const int* in_sizes, int n_in,
                              void* d_out, int out_size)
{
    const float* motions = (const float*)d_in[0];
    const float* z       = (const float*)d_in[1];
    const float* gw1     = (const float*)d_in[2];
    const float* gb1     = (const float*)d_in[3];
    const float* gw2     = (const float*)d_in[4];
    const float* gb2     = (const float*)d_in[5];
    const float* gw3     = (const float*)d_in[6];
    const float* gb3     = (const float*)d_in[7];
    const float* W1      = (const float*)d_in[8];
    const float* b1      = (const float*)d_in[9];
    const float* W2      = (const float*)d_in[10];
    const float* b2      = (const float*)d_in[11];
    const float* W3      = (const float*)d_in[12];
    const float* b3      = (const float*)d_in[13];
    float* out = (float*)d_out;

    void *pX, *pZ, *pgw1, *pgw2, *pgw3, *pW1, *pW2, *pW3;
    void *pG1, *pG2, *pH1, *pH2, *pH3, *ppara;
    cudaGetSymbolAddress(&pX,   g_X);
    cudaGetSymbolAddress(&pZ,   g_Zb);
    cudaGetSymbolAddress(&pgw1, g_gw1);
    cudaGetSymbolAddress(&pgw2, g_gw2);
    cudaGetSymbolAddress(&pgw3, g_gw3);
    cudaGetSymbolAddress(&pW1,  g_W1);
    cudaGetSymbolAddress(&pW2,  g_W2);
    cudaGetSymbolAddress(&pW3,  g_W3);
    cudaGetSymbolAddress(&pG1,  g_G1);
    cudaGetSymbolAddress(&pG2,  g_G2);
    cudaGetSymbolAddress(&pH1,  g_H1);
    cudaGetSymbolAddress(&pH2,  g_H2);
    cudaGetSymbolAddress(&pH3,  g_H3);
    cudaGetSymbolAddress(&ppara, g_para);

    typedef __nv_bfloat16 bf;

    // Convert weights to bf16 (vectorized) + build X/Z
    cvt4_kernel<<<144,  256>>>((const float4*)gw1, (uint2*)pgw1, 288 * 512 / 4);
    cvt4_kernel<<<256,  256>>>((const float4*)gw2, (uint2*)pgw2, 512 * 512 / 4);
    cvt4_kernel<<<4,    256>>>((const float4*)gw3, (uint2*)pgw3, 512 * 8 / 4);
    cvt4_kernel<<<2304, 256>>>((const float4*)W1,  (uint2*)pW1,  NEXP * 288 * 512 / 4);
    cvt4_kernel<<<2176, 256>>>((const float4*)W2,  (uint2*)pW2,  NEXP * 544 * 512 / 4);
    cvt4_kernel<<<544,  256>>>((const float4*)W3,  (uint2*)pW3,  NEXP * 544 * 128 / 4);
    buildx_kernel<<<BQ * 288 / 256, 256>>>(motions, z, (bf*)pX, (bf*)pZ);

    // Gate MLP
    gemm_elu<<<dim3(4, 128, 1), 256>>>((bf*)pX, nullptr, (bf*)pgw1, gb1, (bf*)pG1,
                                       512, 288, 0, 0, 0, 0, 0);
    gemm_elu<<<dim3(4, 128, 1), 256>>>((bf*)pG1, nullptr, (bf*)pgw2, gb2, (bf*)pG2,
                                       512, 512, 0, 0, 0, 0, 0);
    gate3_kernel<<<BQ / 8, 256>>>((bf*)pG2, (bf*)pgw3, gb3, (float*)ppara);
    sumsq_kernel<<<256, 256>>>((float*)ppara);
    norminv_kernel<<<1, 256>>>();

    // Experts (blockIdx.z = expert)
    gemm_elu<<<dim3(4, 128, NEXP), 256>>>((bf*)pX, nullptr, (bf*)pW1, b1, (bf*)pH1,
                                          512, 288, 0,
                                          0, (long long)288 * 512, 512, (long long)BQ * 512);
    gemm_elu<<<dim3(4, 128, NEXP), 256>>>((bf*)pH1, (bf*)pZ, (bf*)pW2, b2, (bf*)pH2,
                                          512, 512, 32,
                                          (long long)BQ * 512, (long long)544 * 512, 512,
                                          (long long)BQ * 512);
    gemm_elu<<<dim3(1, 128, NEXP), 256>>>((bf*)pH2, (bf*)pZ, (bf*)pW3, b3, (bf*)pH3,
                                          128, 512, 32,
                                          (long long)BQ * 512, (long long)544 * 128, 128,
                                          (long long)BQ * 128);

    // Gated combine + norm + sigmoid
    final_kernel<<<BQ * 128 / 256, 256>>>((bf*)pH3, (float*)ppara, out);
}